// round 9
// baseline (speedup 1.0000x reference)
#include <cuda_runtime.h>
#include <cuda_bf16.h>
#include <cstdint>
#include <cstddef>

// ---------------------------------------------------------------------------
// TreeRNNCell: out = tanh( mask*(x@W_in + b_in) + segsum(h[src]->dst)@W_aggr + b_aggr )
// N = 500000, E = 500000, X = H = 128.
//
// R8: algebraic restructure — agg@W_aggr = scatter_sum(h@W_aggr):
//   gemm1 (persistent): hW = h @ W_aggr          (bf16 hi/lo 3-term MMA)
//   zero g_agg; scatter: g_agg[dst] += hW[src]   (red.global.add.v4)
//   gemm2 (persistent): out = tanh(x_m @ W_in + g_agg + m*b_in + b_aggr)
// Each GEMM: CTA = 64 rows x 128 cols, 102 KB smem -> 2 CTAs/SM (16 warps),
// W resident across row tiles (persistent grid-stride), warp tile 32x32,
// register double-buffered ldmatrix/mma pipeline.
// ---------------------------------------------------------------------------

#define MAXN 500000
__device__ float g_agg[(size_t)MAXN * 128];
__device__ float g_hw[(size_t)MAXN * 128];
// 4 images: [Win_hi, Win_lo, Wag_hi, Wag_lo], each [128n][64 uint] = bf16x2[n][k]
__device__ __align__(16) unsigned int g_wimg[4 * 8192];

__device__ __forceinline__ float tanh_fast(float x) {
    float r; asm("tanh.approx.f32 %0, %1;" : "=f"(r) : "f"(x)); return r;
}
__device__ __forceinline__ uint32_t smem_u32(const void* p) {
    uint32_t a;
    asm("{ .reg .u64 t; cvta.to.shared.u64 t, %1; cvt.u32.u64 %0, t; }" : "=r"(a) : "l"(p));
    return a;
}
__device__ __forceinline__ uint32_t pack_split(float a, float b, uint32_t& lo) {
    __nv_bfloat16 ha = __float2bfloat16(a), hb = __float2bfloat16(b);
    __nv_bfloat16 la = __float2bfloat16(a - __bfloat162float(ha));
    __nv_bfloat16 lb = __float2bfloat16(b - __bfloat162float(hb));
    lo = ((uint32_t)__bfloat16_as_ushort(lb) << 16) | __bfloat16_as_ushort(la);
    return ((uint32_t)__bfloat16_as_ushort(hb) << 16) | __bfloat16_as_ushort(ha);
}

#define LDSM_X4(r0, r1, r2, r3, addr) \
    asm volatile("ldmatrix.sync.aligned.m8n8.x4.shared.b16 {%0,%1,%2,%3}, [%4];" \
                 : "=r"(r0), "=r"(r1), "=r"(r2), "=r"(r3) : "r"(addr))

#define MMA16816(acc, a0, a1, a2, a3, b0, b1) \
    asm volatile("mma.sync.aligned.m16n8k16.row.col.f32.bf16.bf16.f32 " \
                 "{%0,%1,%2,%3}, {%4,%5,%6,%7}, {%8,%9}, {%0,%1,%2,%3};" \
                 : "+f"((acc)[0]), "+f"((acc)[1]), "+f"((acc)[2]), "+f"((acc)[3]) \
                 : "r"(a0), "r"(a1), "r"(a2), "r"(a3), "r"(b0), "r"(b1))

// smem layout: rows padded to 136 bf16 (272 B) -> conflict-free ldmatrix.
#define ROWB 272u
#define WIMGB (128u * ROWB)          // 34816 per W image
#define AIMGB (64u * ROWB)           // 17408 per A image
#define SM_WH 0u
#define SM_WL WIMGB                  // 34816
#define SM_AH (2u * WIMGB)           // 69632
#define SM_AL (SM_AH + AIMGB)        // 87040
#define SM_TOTAL (SM_AL + AIMGB)     // 104448 (102 KB) -> 2 CTAs/SM

// Load the 8 LDSM.x4 for one k-step into frag buffer `B` (literal index!)
#define LOAD_K(B, kb)                                                          \
    do {                                                                       \
        LDSM_X4(fa[B][0], fa[B][1], fa[B][2], fa[B][3], ahb + (kb));           \
        LDSM_X4(fa[B][4], fa[B][5], fa[B][6], fa[B][7],                        \
                ahb + 16 * ROWB + (kb));                                       \
        LDSM_X4(fa[B][8], fa[B][9], fa[B][10], fa[B][11], alb + (kb));         \
        LDSM_X4(fa[B][12], fa[B][13], fa[B][14], fa[B][15],                    \
                alb + 16 * ROWB + (kb));                                       \
        LDSM_X4(fbh[B][0], fbh[B][1], fbh[B][2], fbh[B][3], whi + (kb));       \
        LDSM_X4(fbh[B][4], fbh[B][5], fbh[B][6], fbh[B][7],                    \
                whi + 16 * ROWB + (kb));                                       \
        LDSM_X4(fbl[B][0], fbl[B][1], fbl[B][2], fbl[B][3], wlo + (kb));       \
        LDSM_X4(fbl[B][4], fbl[B][5], fbl[B][6], fbl[B][7],                    \
                wlo + 16 * ROWB + (kb));                                       \
    } while (0)

// 24 MMAs (hh, lh, hl) on frag buffer `B`; acc[mt][nt][4], mt 0..1, nt 0..3
#define MMA_K(B)                                                               \
    do {                                                                       \
        _Pragma("unroll") for (int nt = 0; nt < 4; nt++) {                     \
            MMA16816(acc[0][nt], fa[B][0], fa[B][1], fa[B][2], fa[B][3],       \
                     fbh[B][2 * nt], fbh[B][2 * nt + 1]);                      \
            MMA16816(acc[1][nt], fa[B][4], fa[B][5], fa[B][6], fa[B][7],       \
                     fbh[B][2 * nt], fbh[B][2 * nt + 1]);                      \
        }                                                                      \
        _Pragma("unroll") for (int nt = 0; nt < 4; nt++) {                     \
            MMA16816(acc[0][nt], fa[B][8], fa[B][9], fa[B][10], fa[B][11],     \
                     fbh[B][2 * nt], fbh[B][2 * nt + 1]);                      \
            MMA16816(acc[1][nt], fa[B][12], fa[B][13], fa[B][14], fa[B][15],   \
                     fbh[B][2 * nt], fbh[B][2 * nt + 1]);                      \
        }                                                                      \
        _Pragma("unroll") for (int nt = 0; nt < 4; nt++) {                     \
            MMA16816(acc[0][nt], fa[B][0], fa[B][1], fa[B][2], fa[B][3],       \
                     fbl[B][2 * nt], fbl[B][2 * nt + 1]);                      \
            MMA16816(acc[1][nt], fa[B][4], fa[B][5], fa[B][6], fa[B][7],       \
                     fbl[B][2 * nt], fbl[B][2 * nt + 1]);                      \
        }                                                                      \
    } while (0)

// ---------------------------------------------------------------------------
// Kernel 0: build bf16 hi/lo W images (plain [n][k-pair] layout)
// ---------------------------------------------------------------------------
__global__ void prep_w(const float* __restrict__ Win, const float* __restrict__ Wag) {
    int n = blockIdx.x;     // output feature 0..127
    int kp = threadIdx.x;   // k-pair 0..63
    int k0 = kp * 2;
    float a0 = Win[k0 * 128 + n], a1 = Win[(k0 + 1) * 128 + n];
    float b0 = Wag[k0 * 128 + n], b1 = Wag[(k0 + 1) * 128 + n];
    uint32_t alo, blo;
    uint32_t ahi = pack_split(a0, a1, alo);
    uint32_t bhi = pack_split(b0, b1, blo);
    int idx = n * 64 + kp;
    g_wimg[0 * 8192 + idx] = ahi;
    g_wimg[1 * 8192 + idx] = alo;
    g_wimg[2 * 8192 + idx] = bhi;
    g_wimg[3 * 8192 + idx] = blo;
}

// ---------------------------------------------------------------------------
// Kernel 1: zero the aggregation scratch
// ---------------------------------------------------------------------------
__global__ void zero_kernel(long long n4) {
    long long i = (long long)blockIdx.x * blockDim.x + threadIdx.x;
    long long stride = (long long)gridDim.x * blockDim.x;
    float4 z = make_float4(0.f, 0.f, 0.f, 0.f);
    float4* p = reinterpret_cast<float4*>(g_agg);
    for (; i < n4; i += stride) p[i] = z;
}

// ---------------------------------------------------------------------------
// Kernel 2: scatter-add  g_agg[dst] += g_hw[src]  (one warp per edge)
// ---------------------------------------------------------------------------
__global__ void scatter_kernel(const int* __restrict__ src,
                               const int* __restrict__ dst, int E) {
    int warp = (blockIdx.x * blockDim.x + threadIdx.x) >> 5;
    int lane = threadIdx.x & 31;
    if (warp >= E) return;
    int s = __ldg(&src[warp]);
    int d = __ldg(&dst[warp]);
    const float4 v = __ldg(reinterpret_cast<const float4*>(g_hw + (size_t)s * 128) + lane);
    float* p = g_agg + (size_t)d * 128 + lane * 4;
    asm volatile("red.global.add.v4.f32 [%0], {%1,%2,%3,%4};"
                 :: "l"(p), "f"(v.x), "f"(v.y), "f"(v.z), "f"(v.w)
                 : "memory");
}

// ---------------------------------------------------------------------------
// GEMM (persistent): CTA = 64 rows x 128 cols; warp tile 32x32 (grid 2x4).
// MODE 0: outp = A @ W            (gemm1: A=h, W=W_aggr pair)
// MODE 1: outp = tanh(A_m @ W + g_agg + m*bin + baggr)  (gemm2: A=x, W=W_in)
// ---------------------------------------------------------------------------
template <int MODE>
__global__ void __launch_bounds__(256, 2) gemm_phase(
    const float* __restrict__ A, const unsigned int* __restrict__ wpair,
    const float* __restrict__ bin, const float* __restrict__ baggr,
    const int* __restrict__ mask, float* __restrict__ outp, int N, int ntiles) {
    extern __shared__ char smem[];
    const uint32_t sbase = smem_u32(smem);
    const int tid = threadIdx.x;
    const int wid = tid >> 5;
    const int lid = tid & 31;

    // ---- copy W hi/lo pair into smem ONCE (persistent CTA) ----
    {
        const uint4* src = reinterpret_cast<const uint4*>(wpair);
#pragma unroll
        for (int it = 0; it < 16; it++) {
            int idx = tid + it * 256;        // 4096 uint4 (2 images)
            int row = idx >> 4;              // 0..255: img*128 + n
            int j = idx & 15;
            int img = row >> 7, n = row & 127;
            *reinterpret_cast<uint4*>(smem + SM_WH + (uint32_t)img * WIMGB +
                                      (uint32_t)n * ROWB + (uint32_t)j * 16) = src[idx];
        }
    }

    // warp tile: rows m0..m0+31, cols n0..n0+31
    const int wr = wid >> 2;       // 0..1
    const int wc = wid & 3;        // 0..3
    const int m0 = wr * 32;
    const int n0 = wc * 32;

    const int l8 = lid & 7;
    const int quad = lid >> 3;
    const uint32_t a_lane_off =
        (uint32_t)((m0 + l8 + (quad & 1) * 8) * ROWB + ((quad >> 1) * 8) * 2);
    const uint32_t b_lane_off =
        (uint32_t)((n0 + l8 + (quad >> 1) * 8) * ROWB + ((quad & 1) * 8) * 2);
    const uint32_t whi = sbase + SM_WH + b_lane_off;
    const uint32_t wlo = sbase + SM_WL + b_lane_off;
    const uint32_t ahb = sbase + SM_AH + a_lane_off;
    const uint32_t alb = sbase + SM_AL + a_lane_off;

    // A-tile loader mapping: thread -> (row 0..63, 32-col chunk)
    const int arow = tid >> 2;
    const int acb = (tid & 3) * 32;

    // epilogue mapping
    const int tq = lid >> 2;   // 0..7
    const int t4 = lid & 3;    // 0..3

    uint32_t fa[2][16], fbh[2][8], fbl[2][8];

    for (int tile = blockIdx.x; tile < ntiles; tile += gridDim.x) {
        const int row0 = tile * 64;
        const int rg = row0 + arow;
        const bool ok = (rg < N);

        // ---- load A rows (global) ----
        float4 av[8];
        {
            const float4* as =
                reinterpret_cast<const float4*>(A + (size_t)(ok ? rg : 0) * 128 + acb);
#pragma unroll
            for (int j = 0; j < 8; j++)
                av[j] = ok ? __ldg(as + j) : make_float4(0.f, 0.f, 0.f, 0.f);
        }
        float mrow = 1.f;
        if (MODE == 1)
            mrow = (ok && (__ldg(&mask[ok ? rg : 0]) != 0)) ? 1.f : 0.f;

        __syncthreads();  // previous tile's LDSMs complete; W copy ordered (tile 0)

        // ---- convert + store A tile (mask folded for MODE 1) ----
#pragma unroll
        for (int j = 0; j < 8; j++) {
            float4 v = av[j];
            if (MODE == 1) { v.x *= mrow; v.y *= mrow; v.z *= mrow; v.w *= mrow; }
            uint32_t lo01, lo23;
            uint32_t hi01 = pack_split(v.x, v.y, lo01);
            uint32_t hi23 = pack_split(v.z, v.w, lo23);
            uint32_t off = (uint32_t)(arow * ROWB + (acb + 4 * j) * 2);
            *reinterpret_cast<uint32_t*>(smem + SM_AH + off) = hi01;
            *reinterpret_cast<uint32_t*>(smem + SM_AH + off + 4) = hi23;
            *reinterpret_cast<uint32_t*>(smem + SM_AL + off) = lo01;
            *reinterpret_cast<uint32_t*>(smem + SM_AL + off + 4) = lo23;
        }
        __syncthreads();

        // ---- accumulators ----
        float acc[2][4][4];
#pragma unroll
        for (int mt = 0; mt < 2; mt++)
#pragma unroll
            for (int nt = 0; nt < 4; nt++) {
                acc[mt][nt][0] = acc[mt][nt][1] = acc[mt][nt][2] = acc[mt][nt][3] = 0.f;
            }

        // ---- pipelined k-loop (8 k-steps) ----
        LOAD_K(0, 0u);
#pragma unroll
        for (int ks = 0; ks < 8; ks += 2) {
            if (ks + 1 < 8) LOAD_K(1, (uint32_t)((ks + 1) * 32));
            MMA_K(0);
            if (ks + 2 < 8) LOAD_K(0, (uint32_t)((ks + 2) * 32));
            MMA_K(1);
        }

        // ---- epilogue ----
#pragma unroll
        for (int mt = 0; mt < 2; mt++) {
            const int r1 = row0 + m0 + mt * 16 + tq;
            const int r2 = r1 + 8;
            if (MODE == 0) {
#pragma unroll
                for (int nt = 0; nt < 4; nt++) {
                    const int c = n0 + nt * 8 + 2 * t4;
                    if (r1 < N) {
                        float2 o; o.x = acc[mt][nt][0]; o.y = acc[mt][nt][1];
                        *reinterpret_cast<float2*>(&outp[(size_t)r1 * 128 + c]) = o;
                    }
                    if (r2 < N) {
                        float2 o; o.x = acc[mt][nt][2]; o.y = acc[mt][nt][3];
                        *reinterpret_cast<float2*>(&outp[(size_t)r2 * 128 + c]) = o;
                    }
                }
            } else {
                const float m1 = (r1 < N && __ldg(&mask[r1 < N ? r1 : 0]) != 0) ? 1.f : 0.f;
                const float m2 = (r2 < N && __ldg(&mask[r2 < N ? r2 : 0]) != 0) ? 1.f : 0.f;
#pragma unroll
                for (int nt = 0; nt < 4; nt++) {
                    const int c = n0 + nt * 8 + 2 * t4;
                    const float bi0 = __ldg(&bin[c]), bi1 = __ldg(&bin[c + 1]);
                    const float ba0 = __ldg(&baggr[c]), ba1 = __ldg(&baggr[c + 1]);
                    if (r1 < N) {
                        float2 ag = *reinterpret_cast<const float2*>(
                            &g_agg[(size_t)r1 * 128 + c]);
                        float2 o;
                        o.x = tanh_fast(acc[mt][nt][0] + ag.x + m1 * bi0 + ba0);
                        o.y = tanh_fast(acc[mt][nt][1] + ag.y + m1 * bi1 + ba1);
                        *reinterpret_cast<float2*>(&outp[(size_t)r1 * 128 + c]) = o;
                    }
                    if (r2 < N) {
                        float2 ag = *reinterpret_cast<const float2*>(
                            &g_agg[(size_t)r2 * 128 + c]);
                        float2 o;
                        o.x = tanh_fast(acc[mt][nt][2] + ag.x + m2 * bi0 + ba0);
                        o.y = tanh_fast(acc[mt][nt][3] + ag.y + m2 * bi1 + ba1);
                        *reinterpret_cast<float2*>(&outp[(size_t)r2 * 128 + c]) = o;
                    }
                }
            }
        }
    }
}

// ---------------------------------------------------------------------------
// Launch
// ---------------------------------------------------------------------------
extern "C" void kernel_launch(void* const* d_in, const int* in_sizes, int n_in,
                              void* d_out, int out_size) {
    const float* x     = (const float*)d_in[0];
    const float* h     = (const float*)d_in[1];
    const float* Win   = (const float*)d_in[2];
    const float* bin   = (const float*)d_in[3];
    const float* Waggr = (const float*)d_in[4];
    const float* baggr = (const float*)d_in[5];
    const int* mask    = (const int*)d_in[6];
    const int* esrc    = (const int*)d_in[7];
    const int* edst    = (const int*)d_in[8];
    float* out = (float*)d_out;

    const int N = in_sizes[0] / 128;
    const int E = in_sizes[7];
    const int ntiles = (N + 63) / 64;

    static int smem_set = 0;
    if (!smem_set) {
        cudaFuncSetAttribute(gemm_phase<0>, cudaFuncAttributeMaxDynamicSharedMemorySize,
                             (int)SM_TOTAL);
        cudaFuncSetAttribute(gemm_phase<1>, cudaFuncAttributeMaxDynamicSharedMemorySize,
                             (int)SM_TOTAL);
        smem_set = 1;
    }

    unsigned int* wimg_dev = nullptr;
    cudaGetSymbolAddress((void**)&wimg_dev, g_wimg);
    float* hw_dev = nullptr;
    cudaGetSymbolAddress((void**)&hw_dev, g_hw);

    prep_w<<<128, 64>>>(Win, Waggr);
    long long n4 = (long long)N * 128 / 4;
    zero_kernel<<<2048, 256>>>(n4);
    // gemm1: hW = h @ W_aggr   (images 2,3)
    gemm_phase<0><<<296, 256, SM_TOTAL>>>(h, wimg_dev + 2 * 8192, nullptr, nullptr,
                                          nullptr, hw_dev, N, ntiles);
    // scatter: g_agg[dst] += hW[src]
    scatter_kernel<<<(E + 7) / 8, 256>>>(esrc, edst, E);
    // gemm2: out = tanh(x_m @ W_in + g_agg + m*b_in + b_aggr)   (images 0,1)
    gemm_phase<1><<<296, 256, SM_TOTAL>>>(x, wimg_dev, bin, baggr, mask, out, N,
                                          ntiles);
}